// round 10
// baseline (speedup 1.0000x reference)
#include <cuda_runtime.h>
#include <cuda_fp16.h>
#include <mma.h>
#include <math.h>
#include <cstdint>
#include <cstdio>

using namespace nvcuda;

// Problem constants
#define DIMC   64
#define KBANK  4
#define BATCH  16
#define HIN    256
#define WIN    256
#define KSZ    5
#define HO     127
#define WO     127
#define OUT_SPATIAL (HO*WO)                       // 16129
#define OUT_OFFSET  (BATCH*DIMC*OUT_SPATIAL)      // start of w_ret in d_out

#define NTAP 25
#define BM   128        // spatial positions per block (8 oy x 16 ox)
#define BN   64         // couts per block
#define LDA  72         // sA leading dim (halves) : 144 B/row
#define LDB  72         // sB leading dim (halves) : 144 B/row
#define LDE  68         // epilogue leading dim (floats)

// Stage sizes (halves)
#define A_HALVES (BM*LDA)          // 9216
#define B_HALVES (64*LDB)          // 4608
#define STAGE_HALVES (A_HALVES + B_HALVES)  // 13824
#define SM_TOTAL (2*STAGE_HALVES*2)         // 55296 bytes

// Scratch (static device arrays — no allocations allowed)
__device__ float  g_pooled[BATCH*DIMC];
__device__ float  g_aggb[BATCH*DIMC];
__device__ float  g_att[BATCH*KBANK];
__device__ __half g_wmat[BATCH*NTAP*DIMC*DIMC];      // [b][s][ci][co], fp16
__device__ __half g_xh[(size_t)BATCH*HIN*WIN*DIMC];  // NHWC fp16 (128 MB)

// ---------------------------------------------------------------------------
// cp.async helpers
// ---------------------------------------------------------------------------
__device__ __forceinline__ void cp16(unsigned saddr, const void* gptr, bool pred) {
    int sz = pred ? 16 : 0;
    asm volatile("cp.async.cg.shared.global [%0], [%1], 16, %2;\n"
                 :: "r"(saddr), "l"(gptr), "r"(sz));
}
__device__ __forceinline__ void cp_commit() {
    asm volatile("cp.async.commit_group;\n");
}
template<int N> __device__ __forceinline__ void cp_wait() {
    asm volatile("cp.async.wait_group %0;\n" :: "n"(N));
}

// ---------------------------------------------------------------------------
// 0a) Zero the pooled accumulator (tiny; also used as a launch-index shim so
//     ncu -s 5 -c 1 lands on the conv kernel)
// ---------------------------------------------------------------------------
__global__ void zero_pool_kernel() { g_pooled[threadIdx.x] = 0.f; }

// ---------------------------------------------------------------------------
// 0b) Transpose NCHW fp32 -> NHWC fp16, fused global-avg-pool partials
// ---------------------------------------------------------------------------
__global__ __launch_bounds__(256) void transpose_kernel(const float* __restrict__ x) {
    __shared__ float s[64][65];
    const int b = blockIdx.z, h = blockIdx.y, w0 = blockIdx.x * 64;
    const int tid = threadIdx.x;
    #pragma unroll
    for (int it = 0; it < 16; it++) {
        int f = it*256 + tid;
        int c = f >> 6, wl = f & 63;
        s[c][wl] = x[(((size_t)(b*DIMC + c))*HIN + h)*WIN + w0 + wl];
    }
    __syncthreads();
    #pragma unroll
    for (int it = 0; it < 8; it++) {
        int f = it*256 + tid;
        int wl = f >> 5, c2 = (f & 31) * 2;
        __half2 v = __floats2half2_rn(s[c2][wl], s[c2+1][wl]);
        *(__half2*)(&g_xh[(((size_t)b*HIN + h)*WIN + (w0 + wl))*DIMC + c2]) = v;
    }
    {
        int c = tid >> 2, q = tid & 3;
        float ps = 0.f;
        #pragma unroll
        for (int i = 0; i < 16; i++) ps += s[c][q*16 + i];
        ps += __shfl_xor_sync(0xffffffffu, ps, 1);
        ps += __shfl_xor_sync(0xffffffffu, ps, 2);
        if (q == 0)
            atomicAdd(&g_pooled[b*DIMC + c], ps * (1.0f / (float)(HIN*WIN)));
    }
}

// ---------------------------------------------------------------------------
// 2) Attention MLP + softmax + aggregated bias
// ---------------------------------------------------------------------------
__global__ void att_kernel(const float* __restrict__ fc1_w, const float* __restrict__ fc1_b,
                           const float* __restrict__ fc2_w, const float* __restrict__ fc2_b,
                           const float* __restrict__ bias) {
    int b = threadIdx.x;
    if (b >= BATCH) return;
    float a[KBANK];
    #pragma unroll
    for (int k = 0; k < KBANK; k++) {
        float s = fc1_b[k];
        for (int c = 0; c < DIMC; c++) s += fc1_w[k*DIMC + c] * g_pooled[b*DIMC + c];
        a[k] = fmaxf(s, 0.f);
    }
    float l[KBANK]; float mx = -1e30f;
    #pragma unroll
    for (int k = 0; k < KBANK; k++) {
        float s = fc2_b[k];
        #pragma unroll
        for (int j = 0; j < KBANK; j++) s += fc2_w[k*KBANK + j] * a[j];
        l[k] = s; mx = fmaxf(mx, s);
    }
    float den = 0.f;
    #pragma unroll
    for (int k = 0; k < KBANK; k++) { l[k] = expf(l[k] - mx); den += l[k]; }
    float inv = 1.0f / den;
    #pragma unroll
    for (int k = 0; k < KBANK; k++) { l[k] *= inv; g_att[b*KBANK + k] = l[k]; }
    for (int o = 0; o < DIMC; o++) {
        float s = 0.f;
        #pragma unroll
        for (int k = 0; k < KBANK; k++) s += l[k] * bias[k*DIMC + o];
        g_aggb[b*DIMC + o] = s;
    }
}

// ---------------------------------------------------------------------------
// 3) Mix kernel banks (read-coalesced R6 form); wmat [b][s][ci][co]
// ---------------------------------------------------------------------------
__global__ void aggw_kernel(const float* __restrict__ weight, float* __restrict__ out) {
    const int PER_B = DIMC*DIMC*KSZ*KSZ;   // 102400
    int idx = blockIdx.x * 256 + threadIdx.x;
    if (idx >= BATCH*PER_B) return;
    int b = idx / PER_B;
    int r = idx - b*PER_B;                 // (o,i,s)
    int o  = r / (DIMC*KSZ*KSZ);
    int r2 = r - o*(DIMC*KSZ*KSZ);
    int i  = r2 / (KSZ*KSZ);
    int s  = r2 - i*(KSZ*KSZ);
    float v = 0.f;
    #pragma unroll
    for (int k = 0; k < KBANK; k++)
        v += g_att[b*KBANK + k] * weight[(size_t)k*PER_B + r];
    out[(size_t)OUT_OFFSET + ((size_t)(b*DIMC + o)*(KSZ*KSZ) + s)*DIMC + i] = v;
    g_wmat[(((size_t)b*NTAP + s)*DIMC + i)*DIMC + o] = __float2half_rn(v);
}

// ---------------------------------------------------------------------------
// 4) Implicit-GEMM conv, fp16 HMMA, per-tap K=64 double-buffered cp.async.
//    Block: 128 spatial (8 oy x 16 ox) x 64 cout; 25 taps x 4 K16-steps.
// ---------------------------------------------------------------------------
__global__ __launch_bounds__(256) void conv_tc_kernel(float* __restrict__ out) {
    extern __shared__ __align__(16) char smem_c[];
    __half* stA[2] = { (__half*)smem_c,
                       (__half*)smem_c + STAGE_HALVES };
    __half* stB[2] = { stA[0] + A_HALVES, stA[1] + A_HALVES };
    float*  epi    = (float*)smem_c;

    const int b   = blockIdx.z;
    const int tx  = blockIdx.x & 7;       // ox tile (16 wide)
    const int ty  = blockIdx.x >> 3;      // oy tile (8 tall)
    const int oy0 = ty * 8;
    const int ox0 = tx * 16;

    const int tid = threadIdx.x;
    const int wid = tid >> 5;
    const int wm  = wid >> 1;             // 0..3 : spatial 32-row group
    const int wn  = wid & 1;              // 0..1 : cout 32-col group

    const __half* __restrict__ xb  = g_xh   + (size_t)b * HIN * WIN * DIMC;
    const __half* __restrict__ wbh = g_wmat + (size_t)b * NTAP * DIMC * DIMC;

    wmma::fragment<wmma::accumulator, 16, 16, 16, float> acc[2][2];
    #pragma unroll
    for (int i = 0; i < 2; i++)
        #pragma unroll
        for (int j = 0; j < 2; j++) wmma::fill_fragment(acc[i][j], 0.0f);

    // A staging: 4 cp16 slots/thread covering 128 pos x 64 ci
    int aOff[4], ibY[4], ibX[4], cig8[4];
    bool vs[4];
    #pragma unroll
    for (int j = 0; j < 4; j++) {
        int f = j*256 + tid;              // 0..1023
        int pos = f >> 3, cig = f & 7;
        int py = pos >> 4, px = pos & 15;
        int oy = oy0 + py, ox = ox0 + px;
        aOff[j] = pos*LDA + cig*8;
        cig8[j] = cig*8;
        ibY[j] = oy*2 - 1; ibX[j] = ox*2 - 1;
        vs[j] = (oy < HO) && (ox < WO);
    }
    // B staging: 2 cp16 slots/thread covering 64 k-rows x 64 co
    int bOff[2], bSrc[2];
    #pragma unroll
    for (int j = 0; j < 2; j++) {
        int f = j*256 + tid;              // 0..511
        int row = f >> 3, cig = f & 7;    // row = ci (k), cig*8 = co chunk
        bOff[j] = row*LDB + cig*8;
        bSrc[j] = row*DIMC + cig*8;
    }

    unsigned aBase[2], bBase[2];
    #pragma unroll
    for (int u = 0; u < 2; u++) {
        aBase[u] = (unsigned)__cvta_generic_to_shared(stA[u]);
        bBase[u] = (unsigned)__cvta_generic_to_shared(stB[u]);
    }

    auto issue = [&](int tap, int st) {
        int ky = tap / KSZ, kx = tap - (tap/KSZ)*KSZ;
        #pragma unroll
        for (int j = 0; j < 4; j++) {
            int iy = ibY[j] + ky, ix = ibX[j] + kx;
            bool p = vs[j] && ((unsigned)iy < HIN) && ((unsigned)ix < WIN);
            const __half* g = p ? (xb + (((size_t)iy*WIN + ix)*DIMC + cig8[j])) : xb;
            cp16(aBase[st] + (unsigned)aOff[j]*2u, g, p);
        }
        const __half* wsrc = wbh + (size_t)tap*DIMC*DIMC;
        #pragma unroll
        for (int j = 0; j < 2; j++)
            cp16(bBase[st] + (unsigned)bOff[j]*2u, wsrc + bSrc[j], true);
        cp_commit();
    };

    issue(0, 0);
    for (int tap = 0; tap < NTAP; tap++) {
        if (tap + 1 < NTAP) { issue(tap + 1, (tap + 1) & 1); cp_wait<1>(); }
        else                { cp_wait<0>(); }
        __syncthreads();

        const __half* sA = stA[tap & 1];
        const __half* sB = stB[tap & 1];
        #pragma unroll
        for (int kk = 0; kk < 4; kk++) {
            wmma::fragment<wmma::matrix_a, 16, 16, 16, __half, wmma::row_major> af[2];
            wmma::fragment<wmma::matrix_b, 16, 16, 16, __half, wmma::row_major> bf[2];
            #pragma unroll
            for (int i = 0; i < 2; i++)
                wmma::load_matrix_sync(af[i], &sA[(wm*32 + i*16)*LDA + kk*16], LDA);
            #pragma unroll
            for (int j = 0; j < 2; j++)
                wmma::load_matrix_sync(bf[j], &sB[(kk*16)*LDB + wn*32 + j*16], LDB);
            #pragma unroll
            for (int i = 0; i < 2; i++)
                #pragma unroll
                for (int j = 0; j < 2; j++)
                    wmma::mma_sync(acc[i][j], af[i], bf[j], acc[i][j]);
        }
        __syncthreads();
    }

    // --- epilogue: stage to smem, remap to (co, spatial), add bias ---
    #pragma unroll
    for (int i = 0; i < 2; i++)
        #pragma unroll
        for (int j = 0; j < 2; j++)
            wmma::store_matrix_sync(&epi[(wm*32 + i*16)*LDE + wn*32 + j*16],
                                    acc[i][j], LDE, wmma::mem_row_major);
    __syncthreads();

    #pragma unroll
    for (int it = 0; it < 32; it++) {
        int idx = it*256 + tid;           // 0..8191
        int pos = idx & 127;
        int co  = idx >> 7;
        int py = pos >> 4, px = pos & 15;
        int oy = oy0 + py, ox = ox0 + px;
        if (oy < HO && ox < WO) {
            out[((size_t)(b*DIMC + co))*OUT_SPATIAL + oy*WO + ox] =
                epi[pos*LDE + co] + g_aggb[b*DIMC + co];
        }
    }
}

// ---------------------------------------------------------------------------
extern "C" void kernel_launch(void* const* d_in, const int* in_sizes, int n_in,
                              void* d_out, int out_size) {
    const float* x     = (const float*)d_in[0];
    const float* fc1_w = (const float*)d_in[1];
    const float* fc1_b = (const float*)d_in[2];
    const float* fc2_w = (const float*)d_in[3];
    const float* fc2_b = (const float*)d_in[4];
    const float* weight= (const float*)d_in[5];
    const float* bias  = (const float*)d_in[6];
    float* out = (float*)d_out;

    cudaFuncSetAttribute(conv_tc_kernel,
                         cudaFuncAttributeMaxDynamicSharedMemorySize, SM_TOTAL);

    // launch twice: idempotent, and shifts conv to launch index 5 for ncu -s 5
    zero_pool_kernel<<<1, BATCH*DIMC>>>();
    zero_pool_kernel<<<1, BATCH*DIMC>>>();
    {
        dim3 g(WIN/64, HIN, BATCH);       // 4 x 256 x 16
        transpose_kernel<<<g, 256>>>(x);
    }
    att_kernel<<<1, 32>>>(fc1_w, fc1_b, fc2_w, fc2_b, bias);
    {
        int n = BATCH*DIMC*DIMC*KSZ*KSZ;
        aggw_kernel<<<(n + 255)/256, 256>>>(weight, out);
    }
    {
        dim3 grid(8 * 16, 1, BATCH);      // 128 spatial tiles x 16 samples
        conv_tc_kernel<<<grid, 256, SM_TOTAL>>>(out);
    }
    (void)in_sizes; (void)n_in; (void)out_size;
}

// round 12
// speedup vs baseline: 1.2369x; 1.2369x over previous
#include <cuda_runtime.h>
#include <cuda_fp16.h>
#include <mma.h>
#include <math.h>
#include <cstdint>
#include <cstdio>

using namespace nvcuda;

// Problem constants
#define DIMC   64
#define KBANK  4
#define BATCH  16
#define HIN    256
#define WIN    256
#define KSZ    5
#define HO     127
#define WO     127
#define OUT_SPATIAL (HO*WO)                       // 16129
#define OUT_OFFSET  (BATCH*DIMC*OUT_SPATIAL)      // start of w_ret in d_out

#define NTAP 25
// Conv (implicit GEMM) tiling — R6-proven config
#define BM 128          // spatial positions per block (8 oy x 16 ox)
#define BN 64           // couts per block
#define BKC 32          // cin chunk per stage
#define LDA 40          // sA leading dim (halves)  : 80 B/row (16B multiple)
#define LDB2 40         // sB leading dim (halves)  : 80 B/row (16B multiple)
#define LDE 68          // epilogue leading dim (floats)
#define NCHUNK (NTAP*2) // 50
#define STAGES 4

// Scratch (static device arrays — no allocations allowed)
__device__ float  g_pooled[BATCH*DIMC];
__device__ float  g_aggb[BATCH*DIMC];
__device__ float  g_att[BATCH*KBANK];
__device__ __align__(16) __half g_wmat[BATCH*NTAP*DIMC*DIMC];      // [b][s][co][ci], fp16
__device__ __align__(16) __half g_xh[(size_t)BATCH*HIN*WIN*DIMC];  // NHWC fp16 (128 MB)

// ---------------------------------------------------------------------------
// cp.async helpers
// ---------------------------------------------------------------------------
__device__ __forceinline__ void cp16(unsigned saddr, const void* gptr, bool pred) {
    int sz = pred ? 16 : 0;
    asm volatile("cp.async.cg.shared.global [%0], [%1], 16, %2;\n"
                 :: "r"(saddr), "l"(gptr), "r"(sz));
}
__device__ __forceinline__ void cp_commit() {
    asm volatile("cp.async.commit_group;\n");
}
template<int N> __device__ __forceinline__ void cp_wait() {
    asm volatile("cp.async.wait_group %0;\n" :: "n"(N));
}

// ---------------------------------------------------------------------------
// 0a) Zero the pooled accumulator
// ---------------------------------------------------------------------------
__global__ void zero_pool_kernel() { g_pooled[threadIdx.x] = 0.f; }

// ---------------------------------------------------------------------------
// 0b) Transpose NCHW fp32 -> NHWC fp16, fused global-avg-pool partials
// ---------------------------------------------------------------------------
__global__ __launch_bounds__(256) void transpose_kernel(const float* __restrict__ x) {
    __shared__ float s[64][65];
    const int b = blockIdx.z, h = blockIdx.y, w0 = blockIdx.x * 64;
    const int tid = threadIdx.x;
    #pragma unroll
    for (int it = 0; it < 16; it++) {
        int f = it*256 + tid;
        int c = f >> 6, wl = f & 63;
        s[c][wl] = x[(((size_t)(b*DIMC + c))*HIN + h)*WIN + w0 + wl];
    }
    __syncthreads();
    #pragma unroll
    for (int it = 0; it < 8; it++) {
        int f = it*256 + tid;
        int wl = f >> 5, c2 = (f & 31) * 2;
        __half2 v = __floats2half2_rn(s[c2][wl], s[c2+1][wl]);
        *(__half2*)(&g_xh[(((size_t)b*HIN + h)*WIN + (w0 + wl))*DIMC + c2]) = v;
    }
    {
        int c = tid >> 2, q = tid & 3;
        float ps = 0.f;
        #pragma unroll
        for (int i = 0; i < 16; i++) ps += s[c][q*16 + i];
        ps += __shfl_xor_sync(0xffffffffu, ps, 1);
        ps += __shfl_xor_sync(0xffffffffu, ps, 2);
        if (q == 0)
            atomicAdd(&g_pooled[b*DIMC + c], ps * (1.0f / (float)(HIN*WIN)));
    }
}

// ---------------------------------------------------------------------------
// 2) Attention MLP + softmax + aggregated bias. One warp per batch sample.
// ---------------------------------------------------------------------------
__global__ __launch_bounds__(512) void att_kernel(
        const float* __restrict__ fc1_w, const float* __restrict__ fc1_b,
        const float* __restrict__ fc2_w, const float* __restrict__ fc2_b,
        const float* __restrict__ bias) {
    const int b   = threadIdx.x >> 5;     // 0..15
    const int lid = threadIdx.x & 31;

    const float p0 = g_pooled[b*DIMC + lid];
    const float p1 = g_pooled[b*DIMC + lid + 32];

    float a[KBANK];
    #pragma unroll
    for (int k = 0; k < KBANK; k++) {
        float s = fc1_w[k*DIMC + lid]*p0 + fc1_w[k*DIMC + lid + 32]*p1;
        #pragma unroll
        for (int o = 16; o > 0; o >>= 1) s += __shfl_xor_sync(0xffffffffu, s, o);
        a[k] = fmaxf(s + fc1_b[k], 0.f);
    }
    float l[KBANK]; float mx = -1e30f;
    #pragma unroll
    for (int k = 0; k < KBANK; k++) {
        float s = fc2_b[k];
        #pragma unroll
        for (int j = 0; j < KBANK; j++) s += fc2_w[k*KBANK + j] * a[j];
        l[k] = s; mx = fmaxf(mx, s);
    }
    float den = 0.f;
    #pragma unroll
    for (int k = 0; k < KBANK; k++) { l[k] = expf(l[k] - mx); den += l[k]; }
    float inv = 1.0f / den;
    #pragma unroll
    for (int k = 0; k < KBANK; k++) l[k] *= inv;
    if (lid < KBANK) g_att[b*KBANK + lid] = l[lid];
    #pragma unroll
    for (int hh = 0; hh < 2; hh++) {
        int o = lid + hh*32;
        float s = 0.f;
        #pragma unroll
        for (int k = 0; k < KBANK; k++) s += l[k] * bias[k*DIMC + o];
        g_aggb[b*DIMC + o] = s;
    }
}

// ---------------------------------------------------------------------------
// 3) Mix kernel banks. Block per (b, o): coalesced reads AND stores.
// ---------------------------------------------------------------------------
__global__ __launch_bounds__(256) void aggw_kernel(const float* __restrict__ weight,
                                                   float* __restrict__ out) {
    __shared__ float tmp[DIMC*NTAP];      // [i][s] : 1600 floats
    const int blk = blockIdx.x;           // b*64 + o
    const int b = blk >> 6;
    const int o = blk & 63;
    const int tid = threadIdx.x;

    float at[KBANK];
    #pragma unroll
    for (int k = 0; k < KBANK; k++) at[k] = g_att[b*KBANK + k];

    const float* wsrc = weight + (size_t)o * (DIMC*NTAP);
    #pragma unroll
    for (int it = 0; it < 7; it++) {
        int idx = it*256 + tid;           // (i*25 + s)
        if (idx < DIMC*NTAP) {
            float v = 0.f;
            #pragma unroll
            for (int k = 0; k < KBANK; k++)
                v += at[k] * wsrc[(size_t)k*(DIMC*DIMC*NTAP) + idx];
            tmp[idx] = v;
        }
    }
    __syncthreads();
    // write phase: idx2 = s*64 + i
    float* wret = out + (size_t)OUT_OFFSET + (size_t)blk * (NTAP*DIMC);
    __half* wm  = g_wmat + ((size_t)b*NTAP*DIMC + o) * DIMC;   // + s*4096 + i
    #pragma unroll
    for (int it = 0; it < 7; it++) {
        int idx2 = it*256 + tid;
        if (idx2 < DIMC*NTAP) {
            int s = idx2 >> 6, i = idx2 & 63;
            float v = tmp[i*NTAP + s];
            wret[idx2] = v;
            wm[(size_t)s*(DIMC*DIMC) + i] = __float2half_rn(v);
        }
    }
}

// ---------------------------------------------------------------------------
// 4) Implicit-GEMM conv: fp16 HMMA, 4-stage cp.async ring, 1 barrier/chunk.
//    B stored [co][ci] (64 x 32, 80B rows) -> matrix_b col_major.
// ---------------------------------------------------------------------------
struct alignas(16) Stage { __half A[BM*LDA]; __half Bv[64*LDB2]; };
union ConvSmem { Stage st[STAGES]; float epi[BM*LDE]; };

__global__ __launch_bounds__(256) void conv_tc_kernel(float* __restrict__ out) {
    __shared__ ConvSmem sm;

    const int b   = blockIdx.z;
    const int tx  = blockIdx.x & 7;       // ox tile (16 wide)
    const int ty  = blockIdx.x >> 3;      // oy tile (8 tall)
    const int oy0 = ty * 8;
    const int ox0 = tx * 16;

    const int tid = threadIdx.x;
    const int wid = tid >> 5;
    const int wm  = wid >> 1;             // 0..3 : spatial 32-row group
    const int wn  = wid & 1;              // 0..1 : cout 32-col group

    const __half* __restrict__ xb  = g_xh   + (size_t)b * HIN * WIN * DIMC;
    const __half* __restrict__ wbh = g_wmat + (size_t)b * NTAP * DIMC * DIMC;

    wmma::fragment<wmma::accumulator, 16, 16, 16, float> acc[2][2];
    #pragma unroll
    for (int i = 0; i < 2; i++)
        #pragma unroll
        for (int j = 0; j < 2; j++) wmma::fill_fragment(acc[i][j], 0.0f);

    // A staging: 2 cp16 slots/thread (128 pos x 32 ci)
    int aOff[2], ibY[2], ibX[2], cig8[2];
    bool vs[2];
    #pragma unroll
    for (int j = 0; j < 2; j++) {
        int f = j*256 + tid;              // 0..511
        int pos = f >> 2, cig = f & 3;
        int py = pos >> 4, px = pos & 15;
        int oy = oy0 + py, ox = ox0 + px;
        aOff[j] = pos*LDA + cig*8;
        cig8[j] = cig*8;
        ibY[j] = oy*2 - 1; ibX[j] = ox*2 - 1;
        vs[j] = (oy < HO) && (ox < WO);
    }
    // B staging: 1 cp16 slot/thread: 64 co-rows x 32 ci (80B rows)
    const int bRow = tid >> 2;            // co 0..63
    const int bCig = (tid & 3) * 8;       // ci chunk (halves)
    const int bOff = bRow*LDB2 + bCig;    // halves; *2 bytes is 16B multiple

    unsigned aBase[STAGES], bBase[STAGES];
    #pragma unroll
    for (int u = 0; u < STAGES; u++) {
        aBase[u] = (unsigned)__cvta_generic_to_shared(&sm.st[u].A[0]);
        bBase[u] = (unsigned)__cvta_generic_to_shared(&sm.st[u].Bv[0]);
    }

    // issue chunk c into stage buf.  chunk c = (tap s2, ci-half ch)
    auto issue = [&](int c_, int buf_) {
        int s2 = c_ >> 1, ch = c_ & 1;
        int ky = s2 / KSZ, kx = s2 - (s2/KSZ)*KSZ;
        #pragma unroll
        for (int j = 0; j < 2; j++) {
            int iy = ibY[j] + ky, ix = ibX[j] + kx;
            bool p = vs[j] && ((unsigned)iy < HIN) && ((unsigned)ix < WIN);
            const __half* g = p ? (xb + (((size_t)iy*WIN + ix)*DIMC + ch*BKC + cig8[j])) : xb;
            cp16(aBase[buf_] + (unsigned)aOff[j]*2u, g, p);
        }
        // wmat [s2][co=bRow][ci = ch*32 + bCig]
        cp16(bBase[buf_] + (unsigned)bOff*2u,
             wbh + (((size_t)s2*DIMC + bRow)*DIMC + ch*BKC + bCig), true);
        cp_commit();
    };

    issue(0, 0); issue(1, 1); issue(2, 2);

    for (int c = 0; c < NCHUNK; c++) {
        cp_wait<2>();
        __syncthreads();
        if (c + 3 < NCHUNK) issue(c + 3, (c + 3) & 3);
        else                cp_commit();

        const __half* sA = sm.st[c & 3].A;
        const __half* sB = sm.st[c & 3].Bv;
        #pragma unroll
        for (int kk = 0; kk < 2; kk++) {
            wmma::fragment<wmma::matrix_a, 16, 16, 16, __half, wmma::row_major> af[2];
            wmma::fragment<wmma::matrix_b, 16, 16, 16, __half, wmma::col_major> bf[2];
            #pragma unroll
            for (int i = 0; i < 2; i++)
                wmma::load_matrix_sync(af[i], &sA[(wm*32 + i*16)*LDA + kk*16], LDA);
            #pragma unroll
            for (int j = 0; j < 2; j++)
                wmma::load_matrix_sync(bf[j], &sB[(wn*32 + j*16)*LDB2 + kk*16], LDB2);
            #pragma unroll
            for (int i = 0; i < 2; i++)
                #pragma unroll
                for (int j = 0; j < 2; j++)
                    wmma::mma_sync(acc[i][j], af[i], bf[j], acc[i][j]);
        }
    }

    // --- epilogue: stage to smem, remap to (co, spatial), add bias ---
    __syncthreads();
    #pragma unroll
    for (int i = 0; i < 2; i++)
        #pragma unroll
        for (int j = 0; j < 2; j++)
            wmma::store_matrix_sync(&sm.epi[(wm*32 + i*16)*LDE + wn*32 + j*16],
                                    acc[i][j], LDE, wmma::mem_row_major);
    __syncthreads();

    #pragma unroll
    for (int it = 0; it < 32; it++) {
        int idx = it*256 + tid;           // 0..8191
        int pos = idx & 127;
        int co  = idx >> 7;
        int py = pos >> 4, px = pos & 15;
        int oy = oy0 + py, ox = ox0 + px;
        if (oy < HO && ox < WO) {
            out[((size_t)(b*DIMC + co))*OUT_SPATIAL + oy*WO + ox] =
                sm.epi[pos*LDE + co] + g_aggb[b*DIMC + co];
        }
    }
}

// ---------------------------------------------------------------------------
extern "C" void kernel_launch(void* const* d_in, const int* in_sizes, int n_in,
                              void* d_out, int out_size) {
    const float* x     = (const float*)d_in[0];
    const float* fc1_w = (const float*)d_in[1];
    const float* fc1_b = (const float*)d_in[2];
    const float* fc2_w = (const float*)d_in[3];
    const float* fc2_b = (const float*)d_in[4];
    const float* weight= (const float*)d_in[5];
    const float* bias  = (const float*)d_in[6];
    float* out = (float*)d_out;

    zero_pool_kernel<<<1, BATCH*DIMC>>>();
    {
        dim3 g(WIN/64, HIN, BATCH);       // 4 x 256 x 16
        transpose_kernel<<<g, 256>>>(x);
    }
    att_kernel<<<1, 512>>>(fc1_w, fc1_b, fc2_w, fc2_b, bias);
    aggw_kernel<<<BATCH*DIMC, 256>>>(weight, out);
    {
        dim3 grid(8 * 16, 1, BATCH);      // 128 spatial tiles x 16 samples
        conv_tc_kernel<<<grid, 256>>>(out);
    }
    (void)in_sizes; (void)n_in; (void)out_size;
}